// round 11
// baseline (speedup 1.0000x reference)
#include <cuda_runtime.h>
#include <cuda_fp16.h>
#include <cstdint>

#define OFF_Q    0ull
#define OFF_LOSS 2097152ull
#define OFF_PERP 2097153ull
#define OFF_ENC  2097154ull
#define OFF_DIST 35651586ull

#define BSTRIDE 136   // u32 stride: conflict-free b-frag LDS

// dynamic smem partition (bytes)
#define SMO_B    0            // uint32[2*32*136] = 34816 B (B hi | B lo; wq reuse)
#define SMO_D    34816        // float[128*68]    = 34816 B (dist staging)
#define SMO_WN   69632        // float[128]  chunk code norms
#define SMO_RMIN 70144        // float[128]
#define SMO_RIDX 70656        // int[128]
#define SMO_LOSS 71168        // float[8]
#define SMO_LAST 71200        // int flag
#define SMEM_BYTES 71232

__device__ int      g_counts[1024];   // zero-init; reset by ticket block
__device__ float    g_loss_sum;
__device__ unsigned g_ticket;

static __device__ __forceinline__ void split2(float x, float y,
                                              uint32_t& hi, uint32_t& lo) {
    __half hx = __float2half_rn(x), hy = __float2half_rn(y);
    float rx = x - __half2float(hx), ry = y - __half2float(hy);
    __half2 h = __halves2half2(hx, hy);
    __half2 l = __floats2half2_rn(rx, ry);
    hi = *(uint32_t*)&h;
    lo = *(uint32_t*)&l;
}

static __device__ __forceinline__ void mma16816(float* c, const uint32_t* a,
                                                uint32_t b0, uint32_t b1) {
    asm volatile(
        "mma.sync.aligned.m16n8k16.row.col.f32.f16.f16.f32 "
        "{%0,%1,%2,%3}, {%4,%5,%6,%7}, {%8,%9}, {%0,%1,%2,%3};"
        : "+f"(c[0]), "+f"(c[1]), "+f"(c[2]), "+f"(c[3])
        : "r"(a[0]), "r"(a[1]), "r"(a[2]), "r"(a[3]), "r"(b0), "r"(b1));
}

// --- k_main: everything ------------------------------------------------------
__global__ __launch_bounds__(256, 2)
void k_main(const float* __restrict__ latent, const float* __restrict__ W,
            float* __restrict__ out) {
    extern __shared__ __align__(16) char sm[];
    uint32_t* SBHI   = (uint32_t*)(sm + SMO_B);
    uint32_t* SBLO   = SBHI + 32 * BSTRIDE;
    float*    s_d    = (float*)(sm + SMO_D);
    float*    s_wn   = (float*)(sm + SMO_WN);
    float*    s_rmin = (float*)(sm + SMO_RMIN);
    int*      s_ridx = (int*)  (sm + SMO_RIDX);
    float*    s_loss = (float*)(sm + SMO_LOSS);
    int*      s_last = (int*)  (sm + SMO_LAST);

    const int tid  = threadIdx.x;
    const int blk  = blockIdx.x;
    const int w    = tid >> 5;
    const int lane = tid & 31;
    const int g    = lane >> 2;
    const int tg   = lane & 3;
    const int b    = blk >> 3;
    const int jb   = (blk & 7) * 128;

    const int row0 = w * 16 + g;
    const int row1 = row0 + 8;

    // staging thread mapping
    const int code = tid >> 1;
    const int gh   = tid & 1;

    // ---- A fragments (hi/lo, resident) + fp32 row norms ----
    uint32_t ah[4][4], al[4][4];
    float xn0 = 0.f, xn1 = 0.f;
    {
        const float* LB = latent + (size_t)b * 65536 + jb;
        #pragma unroll
        for (int k = 0; k < 4; k++) {
            const int n0 = 16 * k + 2 * tg;
            float x00 = __ldcs(&LB[(size_t)(n0    ) * 1024 + row0]);
            float x01 = __ldcs(&LB[(size_t)(n0 + 1) * 1024 + row0]);
            float x10 = __ldcs(&LB[(size_t)(n0    ) * 1024 + row1]);
            float x11 = __ldcs(&LB[(size_t)(n0 + 1) * 1024 + row1]);
            float x20 = __ldcs(&LB[(size_t)(n0 + 8) * 1024 + row0]);
            float x21 = __ldcs(&LB[(size_t)(n0 + 9) * 1024 + row0]);
            float x30 = __ldcs(&LB[(size_t)(n0 + 8) * 1024 + row1]);
            float x31 = __ldcs(&LB[(size_t)(n0 + 9) * 1024 + row1]);
            split2(x00, x01, ah[k][0], al[k][0]);
            split2(x10, x11, ah[k][1], al[k][1]);
            split2(x20, x21, ah[k][2], al[k][2]);
            split2(x30, x31, ah[k][3], al[k][3]);
            xn0 += x00*x00 + x01*x01 + x20*x20 + x21*x21;
            xn1 += x10*x10 + x11*x11 + x30*x30 + x31*x31;
        }
        xn0 += __shfl_xor_sync(~0u, xn0, 1);
        xn0 += __shfl_xor_sync(~0u, xn0, 2);
        xn1 += __shfl_xor_sync(~0u, xn1, 1);
        xn1 += __shfl_xor_sync(~0u, xn1, 2);
    }

    float vmin0 = 3.4e38f, vmin1 = 3.4e38f;
    int   imin0 = 0,       imin1 = 0;
    const float2 zero2 = make_float2(0.f, 0.f);

    for (int ch = 0; ch < 8; ch++) {
        __syncthreads();   // prev chunk's mma + staging reads done

        // ---- stage B chunk from W: split fp16 hi/lo + chunk wnorms ----
        {
            const float4* wp =
                (const float4*)(W + (size_t)(ch * 128 + code) * 64) + gh * 8;
            float wa = 0.f;
            #pragma unroll
            for (int q = 0; q < 8; q++) {
                float4 v = wp[q];
                uint32_t h0, l0, h1, l1;
                split2(v.x, v.y, h0, l0);
                split2(v.z, v.w, h1, l1);
                const int kp = gh * 16 + q * 2;
                SBHI[(kp    ) * BSTRIDE + code] = h0;
                SBHI[(kp + 1) * BSTRIDE + code] = h1;
                SBLO[(kp    ) * BSTRIDE + code] = l0;
                SBLO[(kp + 1) * BSTRIDE + code] = l1;
                wa = fmaf(v.x, v.x, fmaf(v.y, v.y,
                     fmaf(v.z, v.z, fmaf(v.w, v.w, wa))));
            }
            wa += __shfl_xor_sync(~0u, wa, 1);
            if (gh == 0) s_wn[code] = wa;
        }
        __syncthreads();

        // ---- coalesced streaming zero-fill of this chunk's enc slice ----
        {
            float2* eb = (float2*)(out + OFF_ENC) + (size_t)blk * 65536 + ch * 64;
            #pragma unroll
            for (int i = 0; i < 32; i++) {
                const int idx = i * 256 + tid;
                const int r = idx >> 6, c2 = idx & 63;
                __stcs(eb + (size_t)r * 512 + c2, zero2);
            }
        }

        // ---- two col-halves: mma 8 tiles -> stage d in smem -> coalesced STG
        #pragma unroll
        for (int hg = 0; hg < 2; hg++) {
            float acc[8][4];
            #pragma unroll
            for (int tt = 0; tt < 8; tt++) {
                acc[tt][0] = 0.f; acc[tt][1] = 0.f;
                acc[tt][2] = 0.f; acc[tt][3] = 0.f;
            }
            #pragma unroll
            for (int k = 0; k < 4; k++) {
                #pragma unroll
                for (int tt = 0; tt < 8; tt++) {
                    const int nb = (hg * 8 + tt) * 8 + g;
                    const int kp = k * 8 + tg;
                    uint32_t bh0 = SBHI[(kp    ) * BSTRIDE + nb];
                    uint32_t bh1 = SBHI[(kp + 4) * BSTRIDE + nb];
                    uint32_t bl0 = SBLO[(kp    ) * BSTRIDE + nb];
                    uint32_t bl1 = SBLO[(kp + 4) * BSTRIDE + nb];
                    mma16816(acc[tt], ah[k], bh0, bh1);   // hi*hi
                    mma16816(acc[tt], al[k], bh0, bh1);   // lo*hi
                    mma16816(acc[tt], ah[k], bl0, bl1);   // hi*lo
                }
            }
            #pragma unroll
            for (int tt = 0; tt < 8; tt++) {
                const int cl  = tt * 8 + 2 * tg;            // col within half
                const int clc = hg * 64 + cl;               // col within chunk
                const int col = ch * 128 + clc;             // global col
                const float2 wn = *(const float2*)&s_wn[clc];
                float d00 = fmaf(-2.f, acc[tt][0], xn0 + wn.x);
                float d01 = fmaf(-2.f, acc[tt][1], xn0 + wn.y);
                float d10 = fmaf(-2.f, acc[tt][2], xn1 + wn.x);
                float d11 = fmaf(-2.f, acc[tt][3], xn1 + wn.y);
                *(float2*)&s_d[row0 * 68 + cl] = make_float2(d00, d01);
                *(float2*)&s_d[row1 * 68 + cl] = make_float2(d10, d11);
                if (d00 < vmin0) { vmin0 = d00; imin0 = col; }
                if (d01 < vmin0) { vmin0 = d01; imin0 = col + 1; }
                if (d10 < vmin1) { vmin1 = d10; imin1 = col; }
                if (d11 < vmin1) { vmin1 = d11; imin1 = col + 1; }
            }
            __syncthreads();
            // coalesced float2 stores: warp = one row (256B)
            {
                const int r8 = tid >> 5;
                float2* db = (float2*)(out + OFF_DIST) +
                             ((size_t)blk * 128) * 512 + ch * 64 + hg * 32;
                #pragma unroll
                for (int i = 0; i < 16; i++) {
                    const int r = i * 8 + r8;
                    __stcs(&db[(size_t)r * 512 + lane],
                           *(const float2*)&s_d[r * 68 + lane * 2]);
                }
            }
            __syncthreads();   // s_d reusable
        }
    }

    // ---- argmin across tg lanes (rows are warp-exclusive) ----
    #pragma unroll
    for (int off = 1; off <= 2; off <<= 1) {
        float ov0 = __shfl_xor_sync(~0u, vmin0, off);
        int   oi0 = __shfl_xor_sync(~0u, imin0, off);
        if (ov0 < vmin0 || (ov0 == vmin0 && oi0 < imin0)) { vmin0 = ov0; imin0 = oi0; }
        float ov1 = __shfl_xor_sync(~0u, vmin1, off);
        int   oi1 = __shfl_xor_sync(~0u, imin1, off);
        if (ov1 < vmin1 || (ov1 == vmin1 && oi1 < imin1)) { vmin1 = ov1; imin1 = oi1; }
    }
    if (tg == 0) {
        s_rmin[row0] = vmin0; s_ridx[row0] = imin0;
        s_rmin[row1] = vmin1; s_ridx[row1] = imin1;
    }
    __syncthreads();

    if (tid < 128) {
        const int ii = s_ridx[tid];
        atomicAdd(&g_counts[ii], 1);
        out[OFF_ENC + (size_t)(blk * 128 + tid) * 1024 + ii] = 1.f;
        float v = s_rmin[tid];
        #pragma unroll
        for (int off = 16; off > 0; off >>= 1)
            v += __shfl_down_sync(~0u, v, off);
        if ((tid & 31) == 0) s_loss[tid >> 5] = v;
    }
    __syncthreads();
    if (tid == 0)
        atomicAdd(&g_loss_sum, s_loss[0] + s_loss[1] + s_loss[2] + s_loss[3]);

    // ---- quantized gather: stride-129 smem stage, coalesced writes ----
    {
        float* wq = (float*)SBHI;
        const float4* wp = (const float4*)(W + (size_t)s_ridx[code] * 64) + gh * 8;
        #pragma unroll
        for (int q = 0; q < 8; q++) {
            float4 v = wp[q];
            const int kk = (gh * 8 + q) * 4;
            wq[(kk + 0) * 129 + code] = v.x;
            wq[(kk + 1) * 129 + code] = v.y;
            wq[(kk + 2) * 129 + code] = v.z;
            wq[(kk + 3) * 129 + code] = v.w;
        }
        __syncthreads();
        float* qb = out + OFF_Q + (size_t)b * 65536 + jb;
        #pragma unroll
        for (int i = 0; i < 32; i++) {
            const int idx = i * 256 + tid;
            const int n = idx >> 7, rr = idx & 127;
            __stcs(&qb[(size_t)n * 1024 + rr], wq[n * 129 + rr]);
        }
    }

    // ---- ticket: last block computes perplexity + loss, resets scratch ----
    __syncthreads();
    if (tid == 0) {
        __threadfence();
        unsigned t = atomicAdd(&g_ticket, 1u);
        *s_last = (t == (unsigned)(gridDim.x - 1));
    }
    __syncthreads();
    if (*s_last) {
        float part = 0.f;
        #pragma unroll
        for (int i = 0; i < 4; i++) {
            const int k = tid * 4 + i;
            const int c = g_counts[k];
            g_counts[k] = 0;                      // reset for next replay
            const float p = (float)c / 32768.0f;
            part += -p * logf(p + 1e-10f);
        }
        #pragma unroll
        for (int off = 16; off > 0; off >>= 1)
            part += __shfl_down_sync(~0u, part, off);
        if (lane == 0) s_loss[w] = part;
        __syncthreads();
        if (tid == 0) {
            float s = 0.f;
            #pragma unroll
            for (int i = 0; i < 8; i++) s += s_loss[i];
            out[OFF_PERP] = expf(s);
            out[OFF_LOSS] = 0.25f * g_loss_sum / 2097152.0f;
            g_loss_sum = 0.f;                     // reset for next replay
            g_ticket   = 0u;
        }
    }
}

// -----------------------------------------------------------------------------
extern "C" void kernel_launch(void* const* d_in, const int* in_sizes, int n_in,
                              void* d_out, int out_size) {
    const float* latent = (const float*)d_in[0];
    const float* W      = (const float*)d_in[1];
    float* out = (float*)d_out;

    cudaFuncAttributes fa;
    cudaFuncGetAttributes(&fa, k_main);
    if (fa.maxDynamicSharedSizeBytes < SMEM_BYTES)
        cudaFuncSetAttribute(k_main, cudaFuncAttributeMaxDynamicSharedMemorySize,
                             SMEM_BYTES);

    k_main<<<256, 256, SMEM_BYTES>>>(latent, W, out);
}

// round 12
// speedup vs baseline: 1.0954x; 1.0954x over previous
#include <cuda_runtime.h>
#include <cuda_fp16.h>
#include <cstdint>

#define OFF_Q    0ull
#define OFF_LOSS 2097152ull
#define OFF_PERP 2097153ull
#define OFF_ENC  2097154ull
#define OFF_DIST 35651586ull

#define BSTRIDE 136   // u32 stride: conflict-free b-frag LDS

// dynamic smem partition (bytes)
#define SMO_B    0            // uint32[2*32*136] = 34816 B (B hi | B lo; wq reuse)
#define SMO_D    34816        // float[128*132]   = 67584 B (full-width dist staging)
#define SMO_WN   102400       // float[1024]
#define SMO_RMIN 106496       // float[128]
#define SMO_RIDX 107008       // int[128]
#define SMO_LOSS 107520       // float[8]
#define SMEM_BYTES 107552

__device__ int      g_counts[1024];
__device__ float    g_loss_sum;
__device__ float    g_wnorm[1024];
// codebook packed fp16 hi/lo, layout [chunk(8)][kp(32)][code(128)] u32
__device__ __align__(16) uint32_t g_whi[32768];
__device__ __align__(16) uint32_t g_wlo[32768];

static __device__ __forceinline__ void split2(float x, float y,
                                              uint32_t& hi, uint32_t& lo) {
    __half hx = __float2half_rn(x), hy = __float2half_rn(y);
    float rx = x - __half2float(hx), ry = y - __half2float(hy);
    __half2 h = __halves2half2(hx, hy);
    __half2 l = __floats2half2_rn(rx, ry);
    hi = *(uint32_t*)&h;
    lo = *(uint32_t*)&l;
}

static __device__ __forceinline__ void mma16816(float* c, const uint32_t* a,
                                                uint32_t b0, uint32_t b1) {
    asm volatile(
        "mma.sync.aligned.m16n8k16.row.col.f32.f16.f16.f32 "
        "{%0,%1,%2,%3}, {%4,%5,%6,%7}, {%8,%9}, {%0,%1,%2,%3};"
        : "+f"(c[0]), "+f"(c[1]), "+f"(c[2]), "+f"(c[3])
        : "r"(a[0]), "r"(a[1]), "r"(a[2]), "r"(a[3]), "r"(b0), "r"(b1));
}

// --- k_pre: pack codebook fp16 hi/lo + wnorms + scratch reset ----------------
__global__ void k_pre(const float* __restrict__ W) {
    const int t    = blockIdx.x * 256 + threadIdx.x;   // 32768 threads
    const int code = t >> 5;
    const int kp   = t & 31;
    float2 v = ((const float2*)(W + (size_t)code * 64))[kp];
    uint32_t h, l;
    split2(v.x, v.y, h, l);
    const int chunk = code >> 7, c = code & 127;
    g_whi[(chunk * 32 + kp) * 128 + c] = h;
    g_wlo[(chunk * 32 + kp) * 128 + c] = l;
    float s = v.x * v.x + v.y * v.y;
    #pragma unroll
    for (int off = 16; off > 0; off >>= 1)
        s += __shfl_xor_sync(~0u, s, off);
    if (kp == 0) g_wnorm[code] = s;
    if (t < 1024) g_counts[t] = 0;       // replay-deterministic reset
    if (t == 0)   g_loss_sum  = 0.f;
}

// --- k_main: fused distances(mma) + argmin + enc + quantized + loss ---------
__global__ __launch_bounds__(256, 2)
void k_main(const float* __restrict__ latent, const float* __restrict__ W,
            float* __restrict__ out) {
    extern __shared__ __align__(16) char sm[];
    uint32_t* SBHI   = (uint32_t*)(sm + SMO_B);
    uint32_t* SBLO   = SBHI + 32 * BSTRIDE;
    float*    s_d    = (float*)(sm + SMO_D);
    float*    s_wn   = (float*)(sm + SMO_WN);
    float*    s_rmin = (float*)(sm + SMO_RMIN);
    int*      s_ridx = (int*)  (sm + SMO_RIDX);
    float*    s_loss = (float*)(sm + SMO_LOSS);

    const int tid  = threadIdx.x;
    const int blk  = blockIdx.x;
    const int w    = tid >> 5;
    const int lane = tid & 31;
    const int g    = lane >> 2;
    const int tg   = lane & 3;
    const int b    = blk >> 3;
    const int jb   = (blk & 7) * 128;

    const int row0 = w * 16 + g;
    const int row1 = row0 + 8;

    ((float4*)s_wn)[tid] = ((const float4*)g_wnorm)[tid];

    // ---- A fragments (hi/lo, resident) + fp32 row norms ----
    uint32_t ah[4][4], al[4][4];
    float xn0 = 0.f, xn1 = 0.f;
    {
        const float* LB = latent + (size_t)b * 65536 + jb;
        #pragma unroll
        for (int k = 0; k < 4; k++) {
            const int n0 = 16 * k + 2 * tg;
            float x00 = __ldcs(&LB[(size_t)(n0    ) * 1024 + row0]);
            float x01 = __ldcs(&LB[(size_t)(n0 + 1) * 1024 + row0]);
            float x10 = __ldcs(&LB[(size_t)(n0    ) * 1024 + row1]);
            float x11 = __ldcs(&LB[(size_t)(n0 + 1) * 1024 + row1]);
            float x20 = __ldcs(&LB[(size_t)(n0 + 8) * 1024 + row0]);
            float x21 = __ldcs(&LB[(size_t)(n0 + 9) * 1024 + row0]);
            float x30 = __ldcs(&LB[(size_t)(n0 + 8) * 1024 + row1]);
            float x31 = __ldcs(&LB[(size_t)(n0 + 9) * 1024 + row1]);
            split2(x00, x01, ah[k][0], al[k][0]);
            split2(x10, x11, ah[k][1], al[k][1]);
            split2(x20, x21, ah[k][2], al[k][2]);
            split2(x30, x31, ah[k][3], al[k][3]);
            xn0 += x00*x00 + x01*x01 + x20*x20 + x21*x21;
            xn1 += x10*x10 + x11*x11 + x30*x30 + x31*x31;
        }
        xn0 += __shfl_xor_sync(~0u, xn0, 1);
        xn0 += __shfl_xor_sync(~0u, xn0, 2);
        xn1 += __shfl_xor_sync(~0u, xn1, 1);
        xn1 += __shfl_xor_sync(~0u, xn1, 2);
    }

    float vmin0 = 3.4e38f, vmin1 = 3.4e38f;
    int   imin0 = 0,       imin1 = 0;
    const float2 zero2 = make_float2(0.f, 0.f);

    // software-pipelined: stores of chunk ch-1 issue alongside staging of ch
    for (int ch = 0; ch < 8; ch++) {
        // ---- phase M: store prev chunk's staged distances (coalesced) ----
        if (ch > 0) {
            float2* db = (float2*)(out + OFF_DIST) +
                         ((size_t)blk * 128) * 512 + (ch - 1) * 64;
            #pragma unroll
            for (int i = 0; i < 32; i++) {
                const int idx = i * 256 + tid;
                const int r = idx >> 6, c2 = idx & 63;
                __stcs(&db[(size_t)r * 512 + c2],
                       *(const float2*)&s_d[r * 132 + 2 * c2]);
            }
        }
        // ---- phase B: stage prepacked B chunk (LDG.128 -> STS.128) ----
        {
            const uint4* GH = (const uint4*)(g_whi + ch * 4096);
            const uint4* GL = (const uint4*)(g_wlo + ch * 4096);
            #pragma unroll
            for (int q = 0; q < 4; q++) {
                const int idx = tid + q * 256;
                const int kp = idx >> 5, c4 = idx & 31;
                *(uint4*)&SBHI[kp * BSTRIDE + c4 * 4] = GH[idx];
                *(uint4*)&SBLO[kp * BSTRIDE + c4 * 4] = GL[idx];
            }
        }
        // ---- enc zero-fill for this chunk's slice (independent stream) ----
        {
            float2* eb = (float2*)(out + OFF_ENC) + (size_t)blk * 65536 + ch * 64;
            #pragma unroll
            for (int i = 0; i < 32; i++) {
                const int idx = i * 256 + tid;
                const int r = idx >> 6, c2 = idx & 63;
                __stcs(eb + (size_t)r * 512 + c2, zero2);
            }
        }
        __syncthreads();   // staging visible; prev s_d fully consumed

        // ---- phase C: mma both col-halves into full-width s_d ----
        #pragma unroll
        for (int hg = 0; hg < 2; hg++) {
            float acc[8][4];
            #pragma unroll
            for (int tt = 0; tt < 8; tt++) {
                acc[tt][0] = 0.f; acc[tt][1] = 0.f;
                acc[tt][2] = 0.f; acc[tt][3] = 0.f;
            }
            #pragma unroll
            for (int k = 0; k < 4; k++) {
                #pragma unroll
                for (int tt = 0; tt < 8; tt++) {
                    const int nb = (hg * 8 + tt) * 8 + g;
                    const int kp = k * 8 + tg;
                    uint32_t bh0 = SBHI[(kp    ) * BSTRIDE + nb];
                    uint32_t bh1 = SBHI[(kp + 4) * BSTRIDE + nb];
                    uint32_t bl0 = SBLO[(kp    ) * BSTRIDE + nb];
                    uint32_t bl1 = SBLO[(kp + 4) * BSTRIDE + nb];
                    mma16816(acc[tt], ah[k], bh0, bh1);   // hi*hi
                    mma16816(acc[tt], al[k], bh0, bh1);   // lo*hi
                    mma16816(acc[tt], ah[k], bl0, bl1);   // hi*lo
                }
            }
            #pragma unroll
            for (int tt = 0; tt < 8; tt++) {
                const int clc = hg * 64 + tt * 8 + 2 * tg;   // col within chunk
                const int col = ch * 128 + clc;
                const float2 wn = *(const float2*)&s_wn[col];
                float d00 = fmaf(-2.f, acc[tt][0], xn0 + wn.x);
                float d01 = fmaf(-2.f, acc[tt][1], xn0 + wn.y);
                float d10 = fmaf(-2.f, acc[tt][2], xn1 + wn.x);
                float d11 = fmaf(-2.f, acc[tt][3], xn1 + wn.y);
                *(float2*)&s_d[row0 * 132 + clc] = make_float2(d00, d01);
                *(float2*)&s_d[row1 * 132 + clc] = make_float2(d10, d11);
                if (d00 < vmin0) { vmin0 = d00; imin0 = col; }
                if (d01 < vmin0) { vmin0 = d01; imin0 = col + 1; }
                if (d10 < vmin1) { vmin1 = d10; imin1 = col; }
                if (d11 < vmin1) { vmin1 = d11; imin1 = col + 1; }
            }
        }
        __syncthreads();   // s_d complete; SBHI/SBLO consumed
    }
    // ---- drain: store last chunk's distances ----
    {
        float2* db = (float2*)(out + OFF_DIST) +
                     ((size_t)blk * 128) * 512 + 7 * 64;
        #pragma unroll
        for (int i = 0; i < 32; i++) {
            const int idx = i * 256 + tid;
            const int r = idx >> 6, c2 = idx & 63;
            __stcs(&db[(size_t)r * 512 + c2],
                   *(const float2*)&s_d[r * 132 + 2 * c2]);
        }
    }

    // ---- argmin across tg lanes (rows are warp-exclusive) ----
    #pragma unroll
    for (int off = 1; off <= 2; off <<= 1) {
        float ov0 = __shfl_xor_sync(~0u, vmin0, off);
        int   oi0 = __shfl_xor_sync(~0u, imin0, off);
        if (ov0 < vmin0 || (ov0 == vmin0 && oi0 < imin0)) { vmin0 = ov0; imin0 = oi0; }
        float ov1 = __shfl_xor_sync(~0u, vmin1, off);
        int   oi1 = __shfl_xor_sync(~0u, imin1, off);
        if (ov1 < vmin1 || (ov1 == vmin1 && oi1 < imin1)) { vmin1 = ov1; imin1 = oi1; }
    }
    if (tg == 0) {
        s_rmin[row0] = vmin0; s_ridx[row0] = imin0;
        s_rmin[row1] = vmin1; s_ridx[row1] = imin1;
    }
    __syncthreads();

    if (tid < 128) {
        const int ii = s_ridx[tid];
        atomicAdd(&g_counts[ii], 1);
        out[OFF_ENC + (size_t)(blk * 128 + tid) * 1024 + ii] = 1.f;
        float v = s_rmin[tid];
        #pragma unroll
        for (int off = 16; off > 0; off >>= 1)
            v += __shfl_down_sync(~0u, v, off);
        if ((tid & 31) == 0) s_loss[tid >> 5] = v;
    }
    __syncthreads();
    if (tid == 0)
        atomicAdd(&g_loss_sum, s_loss[0] + s_loss[1] + s_loss[2] + s_loss[3]);

    // ---- quantized gather: stride-129 smem stage, coalesced writes ----
    {
        float* wq = (float*)SBHI;
        const int code = tid >> 1, gh = tid & 1;
        const float4* wp = (const float4*)(W + (size_t)s_ridx[code] * 64) + gh * 8;
        #pragma unroll
        for (int q = 0; q < 8; q++) {
            float4 v = wp[q];
            const int kk = (gh * 8 + q) * 4;
            wq[(kk + 0) * 129 + code] = v.x;
            wq[(kk + 1) * 129 + code] = v.y;
            wq[(kk + 2) * 129 + code] = v.z;
            wq[(kk + 3) * 129 + code] = v.w;
        }
        __syncthreads();
        float* qb = out + OFF_Q + (size_t)b * 65536 + jb;
        #pragma unroll
        for (int i = 0; i < 32; i++) {
            const int idx = i * 256 + tid;
            const int n = idx >> 7, rr = idx & 127;
            __stcs(&qb[(size_t)n * 1024 + rr], wq[n * 129 + rr]);
        }
    }
}

// --- k_final: perplexity + loss ----------------------------------------------
__global__ void k_final(float* __restrict__ out) {
    __shared__ float red[1024];
    const int k = threadIdx.x;
    const float p = (float)g_counts[k] / 32768.0f;
    red[k] = -p * logf(p + 1e-10f);
    __syncthreads();
    for (int s = 512; s > 0; s >>= 1) {
        if (k < s) red[k] += red[k + s];
        __syncthreads();
    }
    if (k == 0) {
        out[OFF_PERP] = expf(red[0]);
        out[OFF_LOSS] = 0.25f * g_loss_sum / 2097152.0f;
    }
}

// -----------------------------------------------------------------------------
extern "C" void kernel_launch(void* const* d_in, const int* in_sizes, int n_in,
                              void* d_out, int out_size) {
    const float* latent = (const float*)d_in[0];
    const float* W      = (const float*)d_in[1];
    float* out = (float*)d_out;

    cudaFuncAttributes fa;
    cudaFuncGetAttributes(&fa, k_main);
    if (fa.maxDynamicSharedSizeBytes < SMEM_BYTES)
        cudaFuncSetAttribute(k_main, cudaFuncAttributeMaxDynamicSharedMemorySize,
                             SMEM_BYTES);

    k_pre  <<<128, 256>>>(W);
    k_main <<<256, 256, SMEM_BYTES>>>(latent, W, out);
    k_final<<<1, 1024>>>(out);
}